// round 13
// baseline (speedup 1.0000x reference)
#include <cuda_runtime.h>
#include <cuda_bf16.h>
#include <math.h>
#include <stdint.h>

#define BATCH 8
#define TLEN 4096
#define DDIM 1024
#define SDIM 128
#define CH   128
#define NCH  32
#define MROWS 32768

// ==================== helpers ====================
__device__ __forceinline__ uint32_t smem_u32(const void* p) {
    uint32_t a;
    asm("{ .reg .u64 t; cvta.to.shared.u64 t, %1; cvt.u32.u64 %0, t; }" : "=r"(a) : "l"(p));
    return a;
}
#define SWZ128(off) ((off) ^ (((off) >> 3) & 0x70))

#define CP_ASYNC16(saddr, gptr) \
    asm volatile("cp.async.cg.shared.global [%0], [%1], 16;" :: "r"(saddr), "l"(gptr))
#define CP_COMMIT() asm volatile("cp.async.commit_group;" ::: "memory")
#define CP_WAIT1() asm volatile("cp.async.wait_group 1;" ::: "memory")
#define CP_WAIT0() asm volatile("cp.async.wait_group 0;" ::: "memory")

__device__ __forceinline__ void ldsm4(uint32_t* r, uint32_t addr) {
    asm volatile("ldmatrix.sync.aligned.m8n8.x4.shared.b16 {%0,%1,%2,%3}, [%4];"
        : "=r"(r[0]), "=r"(r[1]), "=r"(r[2]), "=r"(r[3]) : "r"(addr));
}
__device__ __forceinline__ void mma_bf16(float* c, const uint32_t* a, const uint32_t* b) {
    asm volatile("mma.sync.aligned.m16n8k16.row.col.f32.bf16.bf16.f32 "
        "{%0,%1,%2,%3}, {%4,%5,%6,%7}, {%8,%9}, {%0,%1,%2,%3};"
        : "+f"(c[0]), "+f"(c[1]), "+f"(c[2]), "+f"(c[3])
        : "r"(a[0]), "r"(a[1]), "r"(a[2]), "r"(a[3]), "r"(b[0]), "r"(b[1]));
}

// ==================== packed f32x2 helpers ====================
__device__ __forceinline__ unsigned long long pk2(float lo, float hi) {
    unsigned long long r; asm("mov.b64 %0, {%1, %2};" : "=l"(r) : "f"(lo), "f"(hi)); return r;
}
__device__ __forceinline__ void upk2(unsigned long long v, float& lo, float& hi) {
    asm("mov.b64 {%0, %1}, %2;" : "=f"(lo), "=f"(hi) : "l"(v));
}
__device__ __forceinline__ unsigned long long fma2(unsigned long long a, unsigned long long b, unsigned long long c) {
    unsigned long long d; asm("fma.rn.f32x2 %0, %1, %2, %3;" : "=l"(d) : "l"(a), "l"(b), "l"(c)); return d;
}
__device__ __forceinline__ unsigned long long mul2(unsigned long long a, unsigned long long b) {
    unsigned long long d; asm("mul.rn.f32x2 %0, %1, %2;" : "=l"(d) : "l"(a), "l"(b)); return d;
}
__device__ __forceinline__ unsigned long long add2(unsigned long long a, unsigned long long b) {
    unsigned long long d; asm("add.rn.f32x2 %0, %1, %2;" : "=l"(d) : "l"(a), "l"(b)); return d;
}

// ==================== device scratch ====================
__device__ __align__(16) __nv_bfloat16 g_xhi[(size_t)MROWS * DDIM];   // 64 MB
__device__ __align__(16) __nv_bfloat16 g_xlo[(size_t)MROWS * DDIM];   // 64 MB
__device__ __align__(16) __nv_bfloat16 g_ahi[(size_t)MROWS * SDIM];   // 8 MB
__device__ __align__(16) __nv_bfloat16 g_alo[(size_t)MROWS * SDIM];   // 8 MB
__device__ __align__(16) __nv_bfloat16 g_Wt[512 * 3072];              // [n][hi|lo|hi] k-concat
__device__ __align__(16) __nv_bfloat16 g_Wot[1024 * 384];             // [n][hi|lo|hi]
__device__ float g_bcat[512];
__device__ __align__(16) float g_qkvg[(size_t)MROWS * 512];           // q|k|v|sig(g)
__device__ float g_states[(size_t)BATCH * NCH * SDIM * SDIM];
__device__ float g_Dprod[BATCH * NCH * SDIM];
__device__ __align__(16) float g_attn[(size_t)MROWS * SDIM];

// ==================== K0a: pack projection weights (bf16 split, transposed+concat) ====================
__global__ void pack_w_kernel(const float* __restrict__ Wq, const float* __restrict__ Wk,
                              const float* __restrict__ Wv, const float* __restrict__ Wg,
                              const float* __restrict__ bq, const float* __restrict__ bk,
                              const float* __restrict__ bv, const float* __restrict__ bg) {
    int idx = blockIdx.x * 256 + threadIdx.x;
    if (idx < 512 * 1024) {
        int n = idx >> 10, k = idx & 1023;
        int which = n >> 7, s = n & 127;
        const float* W = (which == 0) ? Wq : (which == 1) ? Wk : (which == 2) ? Wv : Wg;
        float w = W[k * SDIM + s];
        __nv_bfloat16 h = __float2bfloat16(w);
        __nv_bfloat16 l = __float2bfloat16(w - __bfloat162float(h));
        size_t row = (size_t)n * 3072;
        g_Wt[row + k] = h;
        g_Wt[row + 1024 + k] = l;
        g_Wt[row + 2048 + k] = h;
    }
    if (idx < 512) {
        int which = idx >> 7, s = idx & 127;
        const float* bp = (which == 0) ? bq : (which == 1) ? bk : (which == 2) ? bv : bg;
        g_bcat[idx] = bp[s];
    }
}

// ==================== K0b: pack Wo ====================
__global__ void pack_wo_kernel(const float* __restrict__ Wo) {
    int idx = blockIdx.x * 256 + threadIdx.x;
    if (idx >= 1024 * 128) return;
    int n = idx >> 7, k = idx & 127;
    float w = Wo[k * 1024 + n];
    __nv_bfloat16 h = __float2bfloat16(w);
    __nv_bfloat16 l = __float2bfloat16(w - __bfloat162float(h));
    size_t row = (size_t)n * 384;
    g_Wot[row + k] = h;
    g_Wot[row + 128 + k] = l;
    g_Wot[row + 256 + k] = h;
}

// ==================== splitters ====================
__device__ __forceinline__ void split4(float4 v, uint2& ho, uint2& lo) {
    __nv_bfloat162 h01 = __floats2bfloat162_rn(v.x, v.y);
    __nv_bfloat162 h23 = __floats2bfloat162_rn(v.z, v.w);
    float2 f01 = __bfloat1622float2(h01);
    float2 f23 = __bfloat1622float2(h23);
    __nv_bfloat162 l01 = __floats2bfloat162_rn(v.x - f01.x, v.y - f01.y);
    __nv_bfloat162 l23 = __floats2bfloat162_rn(v.z - f23.x, v.w - f23.y);
    ho.x = *(uint32_t*)&h01; ho.y = *(uint32_t*)&h23;
    lo.x = *(uint32_t*)&l01; lo.y = *(uint32_t*)&l23;
}

__global__ void split_x_kernel(const float* __restrict__ x) {
    size_t i = (size_t)blockIdx.x * 256 + threadIdx.x;
    float4 v = ((const float4*)x)[i];
    uint2 ho, lo;
    split4(v, ho, lo);
    ((uint2*)g_xhi)[i] = ho;
    ((uint2*)g_xlo)[i] = lo;
}

__global__ void split_attn_kernel() {
    size_t i = (size_t)blockIdx.x * 256 + threadIdx.x;
    float4 v = ((const float4*)g_attn)[i];
    uint2 ho, lo;
    split4(v, ho, lo);
    ((uint2*)g_ahi)[i] = ho;
    ((uint2*)g_alo)[i] = lo;
}

// ==================== HMMA GEMM (bf16x3 split, fp32 accum) ====================
// CTA tile 128x128, 8 warps (4M x 2N, warp tile 32x64), k-chunks of 64 bf16,
// double-buffered smem via cp.async. SW128 swizzle (128B rows).
// EPI 0: C = Xsplit @ Wt  -> bias, sigmoid on g block, write g_qkvg (fp32)
// EPI 1: C = Asplit @ Wot -> + bo + x residual, write yout (fp32)
template<int K0, int EPI>
__global__ void __launch_bounds__(256, 2) gemm_hmma(const float* __restrict__ bias_p,
                                                    const float* __restrict__ xres,
                                                    float* __restrict__ yout) {
    constexpr int CPS = K0 / 64;
    constexpr int NCHUNK = 3 * CPS;
    constexpr int LDB = 3 * K0;
    const __nv_bfloat16* Ahi = (EPI == 0) ? g_xhi : g_ahi;
    const __nv_bfloat16* Alo = (EPI == 0) ? g_xlo : g_alo;
    const __nv_bfloat16* Bc  = (EPI == 0) ? g_Wt  : g_Wot;

    extern __shared__ char smem_raw[];
    const uint32_t sbase = (smem_u32(smem_raw) + 1023) & ~1023u;
    // stage s: A at sbase + s*32768 (16KB), B at +16384 (16KB)

    const int tid = threadIdx.x;
    const int lane = tid & 31, wid = tid >> 5;
    const int bm = blockIdx.x, bn = blockIdx.y;
    const int wm = wid & 3, wn = wid >> 2;
    const int lrow = tid >> 3;     // 0..31
    const int lc16 = tid & 7;      // 16B column

    auto load_chunk = [&](int c, int stage) {
        const int seg = c / CPS;
        const int koff = (c % CPS) * 64;
        const __nv_bfloat16* Aseg = (seg < 2) ? Ahi : Alo;
        const uint32_t sA = sbase + stage * 32768;
        const uint32_t sB = sA + 16384;
        #pragma unroll
        for (int i = 0; i < 4; i++) {
            int row = i * 32 + lrow;
            const __nv_bfloat16* gp = Aseg + (size_t)(bm * 128 + row) * K0 + koff + lc16 * 8;
            CP_ASYNC16(sA + SWZ128((uint32_t)(row * 128 + lc16 * 16)), gp);
        }
        #pragma unroll
        for (int i = 0; i < 4; i++) {
            int row = i * 32 + lrow;
            const __nv_bfloat16* gp = Bc + (size_t)(bn * 128 + row) * LDB + seg * K0 + koff + lc16 * 8;
            CP_ASYNC16(sB + SWZ128((uint32_t)(row * 128 + lc16 * 16)), gp);
        }
        CP_COMMIT();
    };

    float acc[2][8][4];
    #pragma unroll
    for (int mi = 0; mi < 2; mi++)
        #pragma unroll
        for (int nf = 0; nf < 8; nf++)
            #pragma unroll
            for (int q = 0; q < 4; q++) acc[mi][nf][q] = 0.f;

    load_chunk(0, 0);

    #pragma unroll 1
    for (int c = 0; c < NCHUNK; c++) {
        const int stage = c & 1;
        if (c + 1 < NCHUNK) {
            load_chunk(c + 1, stage ^ 1);
            CP_WAIT1();
        } else {
            CP_WAIT0();
        }
        __syncthreads();

        const uint32_t sA = sbase + stage * 32768;
        const uint32_t sB = sA + 16384;
        const int krow = lane & 15;
        const int khalf = ((lane >> 4) & 1) * 16;

        #pragma unroll
        for (int ks = 0; ks < 4; ks++) {
            const int kb = ks * 32 + khalf;
            uint32_t af[2][4], bf[8][2];
            #pragma unroll
            for (int mi = 0; mi < 2; mi++) {
                int row = wm * 32 + mi * 16 + krow;
                ldsm4(af[mi], sA + SWZ128((uint32_t)(row * 128 + kb)));
            }
            #pragma unroll
            for (int gi = 0; gi < 4; gi++) {
                uint32_t r[4];
                int row = wn * 64 + gi * 16 + krow;
                ldsm4(r, sB + SWZ128((uint32_t)(row * 128 + kb)));
                bf[gi * 2][0]     = r[0]; bf[gi * 2][1]     = r[2];
                bf[gi * 2 + 1][0] = r[1]; bf[gi * 2 + 1][1] = r[3];
            }
            #pragma unroll
            for (int mi = 0; mi < 2; mi++)
                #pragma unroll
                for (int nf = 0; nf < 8; nf++)
                    mma_bf16(acc[mi][nf], af[mi], bf[nf]);
        }
        __syncthreads();
    }

    // ---- epilogue ----
    const int r0base = bm * 128 + wm * 32 + (lane >> 2);
    #pragma unroll
    for (int mi = 0; mi < 2; mi++) {
        const int ra = r0base + mi * 16;
        const int rb = ra + 8;
        #pragma unroll
        for (int nf = 0; nf < 8; nf++) {
            const int col = bn * 128 + wn * 64 + nf * 8 + (lane & 3) * 2;
            float c0 = acc[mi][nf][0], c1 = acc[mi][nf][1];
            float c2 = acc[mi][nf][2], c3 = acc[mi][nf][3];
            if (EPI == 0) {
                const float b0 = g_bcat[col], b1 = g_bcat[col + 1];
                float t0 = c0 + b0, t1 = c1 + b1, t2 = c2 + b0, t3 = c3 + b1;
                if (col >= 384) {
                    t0 = 1.0f / (1.0f + expf(-t0));
                    t1 = 1.0f / (1.0f + expf(-t1));
                    t2 = 1.0f / (1.0f + expf(-t2));
                    t3 = 1.0f / (1.0f + expf(-t3));
                }
                *(float2*)(g_qkvg + (size_t)ra * 512 + col) = make_float2(t0, t1);
                *(float2*)(g_qkvg + (size_t)rb * 512 + col) = make_float2(t2, t3);
            } else {
                const float b0 = bias_p[col], b1 = bias_p[col + 1];
                float2 xa = *(const float2*)(xres + (size_t)ra * 1024 + col);
                float2 xb = *(const float2*)(xres + (size_t)rb * 1024 + col);
                *(float2*)(yout + (size_t)ra * 1024 + col) = make_float2(c0 + b0 + xa.x, c1 + b1 + xa.y);
                *(float2*)(yout + (size_t)rb * 1024 + col) = make_float2(c2 + b0 + xb.x, c3 + b1 + xb.y);
            }
        }
    }
}

// ==================== K2: per-chunk local state from zero (+decay products folded) ====================
__global__ void __launch_bounds__(256, 2) chunk_local_kernel() {
    const int c = blockIdx.x, b = blockIdx.y;
    const int tid = threadIdx.x;
    const int j = tid & 127;
    const int half = tid >> 7;
    const int sb = half * 64;

    __shared__ __align__(16) float buf[2][512];
    const float* base = g_qkvg + (size_t)(b * TLEN + c * CH) * 512;

    ((float2*)buf[0])[tid] = ((const float2*)base)[tid];
    __syncthreads();

    unsigned long long st2[32];
    #pragma unroll
    for (int i = 0; i < 32; i++) st2[i] = 0ull;
    float prod = 1.0f;

    for (int t = 0; t < CH; t++) {
        const float* cur = buf[t & 1];
        if (t + 1 < CH)
            ((float2*)buf[(t + 1) & 1])[tid] = ((const float2*)(base + (size_t)(t + 1) * 512))[tid];

        float vj = cur[256 + j];
        if (half == 0) prod *= cur[384 + j];
        unsigned long long vd = pk2(vj, vj);
        #pragma unroll
        for (int sq = 0; sq < 16; sq++) {
            int s = sb + sq * 4;
            ulonglong2 g4 = *(const ulonglong2*)&cur[384 + s];
            ulonglong2 k4 = *(const ulonglong2*)&cur[128 + s];
            st2[2 * sq]     = fma2(g4.x, st2[2 * sq],     mul2(k4.x, vd));
            st2[2 * sq + 1] = fma2(g4.y, st2[2 * sq + 1], mul2(k4.y, vd));
        }
        __syncthreads();
    }

    float* out = g_states + ((size_t)(b * NCH + c) * SDIM + sb) * SDIM + j;
    #pragma unroll
    for (int sp = 0; sp < 32; sp++) {
        float lo, hi;
        upk2(st2[sp], lo, hi);
        out[(size_t)(2 * sp) * SDIM]     = lo;
        out[(size_t)(2 * sp + 1) * SDIM] = hi;
    }
    if (half == 0) g_Dprod[(b * NCH + c) * SDIM + j] = prod;
}

// ==================== K3: sequential scan over chunks ====================
__global__ void scan_states_kernel() {
    const int b = blockIdx.y;
    const int pos = blockIdx.x * 256 + threadIdx.x;
    const int s = pos >> 7, j = pos & 127;
    float run = 0.f;
    for (int c = 0; c < NCH; c++) {
        size_t off = ((size_t)(b * NCH + c) * SDIM + s) * SDIM + j;
        float local = g_states[off];
        g_states[off] = run;
        run = g_Dprod[(b * NCH + c) * SDIM + s] * run + local;
    }
}

// ==================== K4: chunk replay with outputs ====================
__global__ void __launch_bounds__(256, 2) chunk_out_kernel() {
    const int c = blockIdx.x, b = blockIdx.y;
    const int tid = threadIdx.x;
    const int j = tid & 127;
    const int half = tid >> 7;
    const int sb = half * 64;

    __shared__ __align__(16) float buf[2][512];
    __shared__ float po[128];

    const float* base = g_qkvg + (size_t)(b * TLEN + c * CH) * 512;
    float* aout = g_attn + (size_t)(b * TLEN + c * CH) * SDIM;

    const float* sin = g_states + ((size_t)(b * NCH + c) * SDIM + sb) * SDIM + j;
    unsigned long long st2[32];
    #pragma unroll
    for (int sp = 0; sp < 32; sp++)
        st2[sp] = pk2(sin[(size_t)(2 * sp) * SDIM], sin[(size_t)(2 * sp + 1) * SDIM]);

    ((float2*)buf[0])[tid] = ((const float2*)base)[tid];
    __syncthreads();

    for (int t = 0; t < CH; t++) {
        const float* cur = buf[t & 1];
        if (t + 1 < CH)
            ((float2*)buf[(t + 1) & 1])[tid] = ((const float2*)(base + (size_t)(t + 1) * 512))[tid];

        float vj = cur[256 + j];
        unsigned long long vd = pk2(vj, vj);
        unsigned long long accA = 0ull, accB = 0ull;
        #pragma unroll
        for (int sq = 0; sq < 16; sq++) {
            int s = sb + sq * 4;
            ulonglong2 g4 = *(const ulonglong2*)&cur[384 + s];
            ulonglong2 k4 = *(const ulonglong2*)&cur[128 + s];
            ulonglong2 q4 = *(const ulonglong2*)&cur[s];
            st2[2 * sq]     = fma2(g4.x, st2[2 * sq],     mul2(k4.x, vd));
            st2[2 * sq + 1] = fma2(g4.y, st2[2 * sq + 1], mul2(k4.y, vd));
            accA = fma2(q4.x, st2[2 * sq],     accA);
            accB = fma2(q4.y, st2[2 * sq + 1], accB);
        }
        unsigned long long accT = add2(accA, accB);
        float lo, hi;
        upk2(accT, lo, hi);
        float part = lo + hi;

        if (half == 0) po[j] = part;
        __syncthreads();
        if (half == 1) aout[(size_t)t * SDIM + j] = part + po[j];
        __syncthreads();
    }
}

// ==================== K6: LayerNorm in place on d_out ====================
__global__ void ln_kernel(const float* __restrict__ gamma, const float* __restrict__ beta,
                          float* __restrict__ y) {
    const int row = blockIdx.x;
    const int tid = threadIdx.x;  // 256
    float4 v = ((float4*)y)[(size_t)row * 256 + tid];
    float s  = v.x + v.y + v.z + v.w;
    float sq = v.x * v.x + v.y * v.y + v.z * v.z + v.w * v.w;
    #pragma unroll
    for (int o = 16; o; o >>= 1) {
        s  += __shfl_xor_sync(0xffffffffu, s, o);
        sq += __shfl_xor_sync(0xffffffffu, sq, o);
    }
    __shared__ float ws[8], wq[8];
    int w = tid >> 5, l = tid & 31;
    if (l == 0) { ws[w] = s; wq[w] = sq; }
    __syncthreads();
    if (tid < 32) {
        s  = (tid < 8) ? ws[tid] : 0.f;
        sq = (tid < 8) ? wq[tid] : 0.f;
        #pragma unroll
        for (int o = 4; o; o >>= 1) {
            s  += __shfl_xor_sync(0xffffffffu, s, o);
            sq += __shfl_xor_sync(0xffffffffu, sq, o);
        }
        if (tid == 0) { ws[0] = s; wq[0] = sq; }
    }
    __syncthreads();
    const float mu = ws[0] * (1.0f / 1024.0f);
    const float var = wq[0] * (1.0f / 1024.0f) - mu * mu;
    const float rs = rsqrtf(var + 1e-5f);
    const int n = tid * 4;
    v.x = (v.x - mu) * rs * gamma[n + 0] + beta[n + 0];
    v.y = (v.y - mu) * rs * gamma[n + 1] + beta[n + 1];
    v.z = (v.z - mu) * rs * gamma[n + 2] + beta[n + 2];
    v.w = (v.w - mu) * rs * gamma[n + 3] + beta[n + 3];
    ((float4*)y)[(size_t)row * 256 + tid] = v;
}

// ==================== launch ====================
#define GEMM_SMEM (65536 + 1024)

extern "C" void kernel_launch(void* const* d_in, const int* in_sizes, int n_in,
                              void* d_out, int out_size) {
    const float* x     = (const float*)d_in[0];
    const float* Wq    = (const float*)d_in[1];
    const float* bq    = (const float*)d_in[2];
    const float* Wk    = (const float*)d_in[3];
    const float* bk    = (const float*)d_in[4];
    const float* Wv    = (const float*)d_in[5];
    const float* bv    = (const float*)d_in[6];
    const float* Wg    = (const float*)d_in[7];
    const float* bg    = (const float*)d_in[8];
    const float* Wo    = (const float*)d_in[9];
    const float* bo    = (const float*)d_in[10];
    const float* gamma = (const float*)d_in[11];
    const float* beta  = (const float*)d_in[12];
    float* out = (float*)d_out;

    cudaFuncSetAttribute(gemm_hmma<1024, 0>, cudaFuncAttributeMaxDynamicSharedMemorySize, GEMM_SMEM);
    cudaFuncSetAttribute(gemm_hmma<128, 1>,  cudaFuncAttributeMaxDynamicSharedMemorySize, GEMM_SMEM);

    pack_w_kernel<<<(512 * 1024 + 255) / 256, 256>>>(Wq, Wk, Wv, Wg, bq, bk, bv, bg);
    pack_wo_kernel<<<(1024 * 128 + 255) / 256, 256>>>(Wo);
    split_x_kernel<<<MROWS * DDIM / 4 / 256, 256>>>(x);

    gemm_hmma<1024, 0><<<dim3(MROWS / 128, 4), 256, GEMM_SMEM>>>(nullptr, nullptr, nullptr);

    chunk_local_kernel<<<dim3(NCH, BATCH), 256>>>();
    scan_states_kernel<<<dim3(SDIM * SDIM / 256, BATCH), 256>>>();
    chunk_out_kernel<<<dim3(NCH, BATCH), 256>>>();

    split_attn_kernel<<<MROWS * SDIM / 4 / 256, 256>>>();
    gemm_hmma<128, 1><<<dim3(MROWS / 128, 8), 256, GEMM_SMEM>>>(bo, x, out);

    ln_kernel<<<MROWS, 256>>>(gamma, beta, out);
}

// round 14
// speedup vs baseline: 1.0070x; 1.0070x over previous
#include <cuda_runtime.h>
#include <cuda_bf16.h>
#include <math.h>
#include <stdint.h>

#define BATCH 8
#define TLEN 4096
#define DDIM 1024
#define SDIM 128
#define CH   128
#define NCH  32
#define MROWS 32768

// ==================== helpers ====================
__device__ __forceinline__ uint32_t smem_u32(const void* p) {
    uint32_t a;
    asm("{ .reg .u64 t; cvta.to.shared.u64 t, %1; cvt.u32.u64 %0, t; }" : "=r"(a) : "l"(p));
    return a;
}
#define SWZ128(off) ((off) ^ (((off) >> 3) & 0x70))

#define CP_ASYNC16(saddr, gptr) \
    asm volatile("cp.async.cg.shared.global [%0], [%1], 16;" :: "r"(saddr), "l"(gptr))
#define CP_COMMIT() asm volatile("cp.async.commit_group;" ::: "memory")
#define CP_WAIT1() asm volatile("cp.async.wait_group 1;" ::: "memory")
#define CP_WAIT0() asm volatile("cp.async.wait_group 0;" ::: "memory")

__device__ __forceinline__ void ldsm4(uint32_t* r, uint32_t addr) {
    asm volatile("ldmatrix.sync.aligned.m8n8.x4.shared.b16 {%0,%1,%2,%3}, [%4];"
        : "=r"(r[0]), "=r"(r[1]), "=r"(r[2]), "=r"(r[3]) : "r"(addr));
}
__device__ __forceinline__ void mma_bf16(float* c, const uint32_t* a, const uint32_t* b) {
    asm volatile("mma.sync.aligned.m16n8k16.row.col.f32.bf16.bf16.f32 "
        "{%0,%1,%2,%3}, {%4,%5,%6,%7}, {%8,%9}, {%0,%1,%2,%3};"
        : "+f"(c[0]), "+f"(c[1]), "+f"(c[2]), "+f"(c[3])
        : "r"(a[0]), "r"(a[1]), "r"(a[2]), "r"(a[3]), "r"(b[0]), "r"(b[1]));
}

// ==================== packed f32x2 helpers ====================
__device__ __forceinline__ unsigned long long pk2(float lo, float hi) {
    unsigned long long r; asm("mov.b64 %0, {%1, %2};" : "=l"(r) : "f"(lo), "f"(hi)); return r;
}
__device__ __forceinline__ void upk2(unsigned long long v, float& lo, float& hi) {
    asm("mov.b64 {%0, %1}, %2;" : "=f"(lo), "=f"(hi) : "l"(v));
}
__device__ __forceinline__ unsigned long long fma2(unsigned long long a, unsigned long long b, unsigned long long c) {
    unsigned long long d; asm("fma.rn.f32x2 %0, %1, %2, %3;" : "=l"(d) : "l"(a), "l"(b), "l"(c)); return d;
}
__device__ __forceinline__ unsigned long long mul2(unsigned long long a, unsigned long long b) {
    unsigned long long d; asm("mul.rn.f32x2 %0, %1, %2;" : "=l"(d) : "l"(a), "l"(b)); return d;
}
__device__ __forceinline__ unsigned long long add2(unsigned long long a, unsigned long long b) {
    unsigned long long d; asm("add.rn.f32x2 %0, %1, %2;" : "=l"(d) : "l"(a), "l"(b)); return d;
}

// ==================== device scratch ====================
__device__ __align__(16) __nv_bfloat16 g_xhi[(size_t)MROWS * DDIM];   // 64 MB
__device__ __align__(16) __nv_bfloat16 g_xlo[(size_t)MROWS * DDIM];   // 64 MB
__device__ __align__(16) __nv_bfloat16 g_ahi[(size_t)MROWS * SDIM];   // 8 MB
__device__ __align__(16) __nv_bfloat16 g_alo[(size_t)MROWS * SDIM];   // 8 MB
__device__ __align__(16) __nv_bfloat16 g_Wt[512 * 3072];              // [n][hi|lo|hi] k-concat
__device__ __align__(16) __nv_bfloat16 g_Wot[1024 * 384];             // [n][hi|lo|hi]
__device__ float g_bcat[512];
__device__ __align__(16) float g_qkvg[(size_t)MROWS * 512];           // q|k|v|sig(g)
__device__ float g_states[(size_t)BATCH * NCH * SDIM * SDIM];
__device__ float g_Dprod[BATCH * NCH * SDIM];
__device__ __align__(16) float g_attn[(size_t)MROWS * SDIM];

// ==================== K0a: pack projection weights (bf16 split, transposed+concat) ====================
__global__ void pack_w_kernel(const float* __restrict__ Wq, const float* __restrict__ Wk,
                              const float* __restrict__ Wv, const float* __restrict__ Wg,
                              const float* __restrict__ bq, const float* __restrict__ bk,
                              const float* __restrict__ bv, const float* __restrict__ bg) {
    int idx = blockIdx.x * 256 + threadIdx.x;
    if (idx < 512 * 1024) {
        int n = idx >> 10, k = idx & 1023;
        int which = n >> 7, s = n & 127;
        const float* W = (which == 0) ? Wq : (which == 1) ? Wk : (which == 2) ? Wv : Wg;
        float w = W[k * SDIM + s];
        __nv_bfloat16 h = __float2bfloat16(w);
        __nv_bfloat16 l = __float2bfloat16(w - __bfloat162float(h));
        size_t row = (size_t)n * 3072;
        g_Wt[row + k] = h;
        g_Wt[row + 1024 + k] = l;
        g_Wt[row + 2048 + k] = h;
    }
    if (idx < 512) {
        int which = idx >> 7, s = idx & 127;
        const float* bp = (which == 0) ? bq : (which == 1) ? bk : (which == 2) ? bv : bg;
        g_bcat[idx] = bp[s];
    }
}

// ==================== K0b: pack Wo ====================
__global__ void pack_wo_kernel(const float* __restrict__ Wo) {
    int idx = blockIdx.x * 256 + threadIdx.x;
    if (idx >= 1024 * 128) return;
    int n = idx >> 7, k = idx & 127;
    float w = Wo[k * 1024 + n];
    __nv_bfloat16 h = __float2bfloat16(w);
    __nv_bfloat16 l = __float2bfloat16(w - __bfloat162float(h));
    size_t row = (size_t)n * 384;
    g_Wot[row + k] = h;
    g_Wot[row + 128 + k] = l;
    g_Wot[row + 256 + k] = h;
}

// ==================== splitters ====================
__device__ __forceinline__ void split4(float4 v, uint2& ho, uint2& lo) {
    __nv_bfloat162 h01 = __floats2bfloat162_rn(v.x, v.y);
    __nv_bfloat162 h23 = __floats2bfloat162_rn(v.z, v.w);
    float2 f01 = __bfloat1622float2(h01);
    float2 f23 = __bfloat1622float2(h23);
    __nv_bfloat162 l01 = __floats2bfloat162_rn(v.x - f01.x, v.y - f01.y);
    __nv_bfloat162 l23 = __floats2bfloat162_rn(v.z - f23.x, v.w - f23.y);
    ho.x = *(uint32_t*)&h01; ho.y = *(uint32_t*)&h23;
    lo.x = *(uint32_t*)&l01; lo.y = *(uint32_t*)&l23;
}

__global__ void split_x_kernel(const float* __restrict__ x) {
    size_t i = (size_t)blockIdx.x * 256 + threadIdx.x;
    float4 v = ((const float4*)x)[i];
    uint2 ho, lo;
    split4(v, ho, lo);
    ((uint2*)g_xhi)[i] = ho;
    ((uint2*)g_xlo)[i] = lo;
}

__global__ void split_attn_kernel() {
    size_t i = (size_t)blockIdx.x * 256 + threadIdx.x;
    float4 v = ((const float4*)g_attn)[i];
    uint2 ho, lo;
    split4(v, ho, lo);
    ((uint2*)g_ahi)[i] = ho;
    ((uint2*)g_alo)[i] = lo;
}

// ==================== HMMA GEMM (bf16x3 split, fp32 accum) ====================
// CTA tile 128x128, 8 warps (4M x 2N, warp tile 32x64), k-chunks of 64 bf16,
// double-buffered smem via cp.async. SW128 swizzle (128B rows).
// EPI 0: C = Xsplit @ Wt  -> bias, sigmoid on g block, write g_qkvg (fp32)
// EPI 1: C = Asplit @ Wot -> + bo + x residual, write yout (fp32)
template<int K0, int EPI>
__global__ void __launch_bounds__(256, 2) gemm_hmma(const float* __restrict__ bias_p,
                                                    const float* __restrict__ xres,
                                                    float* __restrict__ yout) {
    constexpr int CPS = K0 / 64;
    constexpr int NCHUNK = 3 * CPS;
    constexpr int LDB = 3 * K0;
    const __nv_bfloat16* Ahi = (EPI == 0) ? g_xhi : g_ahi;
    const __nv_bfloat16* Alo = (EPI == 0) ? g_xlo : g_alo;
    const __nv_bfloat16* Bc  = (EPI == 0) ? g_Wt  : g_Wot;

    extern __shared__ char smem_raw[];
    const uint32_t sbase = (smem_u32(smem_raw) + 1023) & ~1023u;
    // stage s: A at sbase + s*32768 (16KB), B at +16384 (16KB)

    const int tid = threadIdx.x;
    const int lane = tid & 31, wid = tid >> 5;
    const int bm = blockIdx.x, bn = blockIdx.y;
    const int wm = wid & 3, wn = wid >> 2;
    const int lrow = tid >> 3;     // 0..31
    const int lc16 = tid & 7;      // 16B column

    auto load_chunk = [&](int c, int stage) {
        const int seg = c / CPS;
        const int koff = (c % CPS) * 64;
        const __nv_bfloat16* Aseg = (seg < 2) ? Ahi : Alo;
        const uint32_t sA = sbase + stage * 32768;
        const uint32_t sB = sA + 16384;
        #pragma unroll
        for (int i = 0; i < 4; i++) {
            int row = i * 32 + lrow;
            const __nv_bfloat16* gp = Aseg + (size_t)(bm * 128 + row) * K0 + koff + lc16 * 8;
            CP_ASYNC16(sA + SWZ128((uint32_t)(row * 128 + lc16 * 16)), gp);
        }
        #pragma unroll
        for (int i = 0; i < 4; i++) {
            int row = i * 32 + lrow;
            const __nv_bfloat16* gp = Bc + (size_t)(bn * 128 + row) * LDB + seg * K0 + koff + lc16 * 8;
            CP_ASYNC16(sB + SWZ128((uint32_t)(row * 128 + lc16 * 16)), gp);
        }
        CP_COMMIT();
    };

    float acc[2][8][4];
    #pragma unroll
    for (int mi = 0; mi < 2; mi++)
        #pragma unroll
        for (int nf = 0; nf < 8; nf++)
            #pragma unroll
            for (int q = 0; q < 4; q++) acc[mi][nf][q] = 0.f;

    load_chunk(0, 0);

    #pragma unroll 1
    for (int c = 0; c < NCHUNK; c++) {
        const int stage = c & 1;
        if (c + 1 < NCHUNK) {
            load_chunk(c + 1, stage ^ 1);
            CP_WAIT1();
        } else {
            CP_WAIT0();
        }
        __syncthreads();

        const uint32_t sA = sbase + stage * 32768;
        const uint32_t sB = sA + 16384;
        const int krow = lane & 15;
        const int khalf = ((lane >> 4) & 1) * 16;

        #pragma unroll
        for (int ks = 0; ks < 4; ks++) {
            const int kb = ks * 32 + khalf;
            uint32_t af[2][4], bf[8][2];
            #pragma unroll
            for (int mi = 0; mi < 2; mi++) {
                int row = wm * 32 + mi * 16 + krow;
                ldsm4(af[mi], sA + SWZ128((uint32_t)(row * 128 + kb)));
            }
            #pragma unroll
            for (int gi = 0; gi < 4; gi++) {
                uint32_t r[4];
                int row = wn * 64 + gi * 16 + krow;
                ldsm4(r, sB + SWZ128((uint32_t)(row * 128 + kb)));
                bf[gi * 2][0]     = r[0]; bf[gi * 2][1]     = r[2];
                bf[gi * 2 + 1][0] = r[1]; bf[gi * 2 + 1][1] = r[3];
            }
            #pragma unroll
            for (int mi = 0; mi < 2; mi++)
                #pragma unroll
                for (int nf = 0; nf < 8; nf++)
                    mma_bf16(acc[mi][nf], af[mi], bf[nf]);
        }
        __syncthreads();
    }

    // ---- epilogue ----
    const int r0base = bm * 128 + wm * 32 + (lane >> 2);
    #pragma unroll
    for (int mi = 0; mi < 2; mi++) {
        const int ra = r0base + mi * 16;
        const int rb = ra + 8;
        #pragma unroll
        for (int nf = 0; nf < 8; nf++) {
            const int col = bn * 128 + wn * 64 + nf * 8 + (lane & 3) * 2;
            float c0 = acc[mi][nf][0], c1 = acc[mi][nf][1];
            float c2 = acc[mi][nf][2], c3 = acc[mi][nf][3];
            if (EPI == 0) {
                const float b0 = g_bcat[col], b1 = g_bcat[col + 1];
                float t0 = c0 + b0, t1 = c1 + b1, t2 = c2 + b0, t3 = c3 + b1;
                if (col >= 384) {
                    t0 = 1.0f / (1.0f + expf(-t0));
                    t1 = 1.0f / (1.0f + expf(-t1));
                    t2 = 1.0f / (1.0f + expf(-t2));
                    t3 = 1.0f / (1.0f + expf(-t3));
                }
                *(float2*)(g_qkvg + (size_t)ra * 512 + col) = make_float2(t0, t1);
                *(float2*)(g_qkvg + (size_t)rb * 512 + col) = make_float2(t2, t3);
            } else {
                const float b0 = bias_p[col], b1 = bias_p[col + 1];
                float2 xa = *(const float2*)(xres + (size_t)ra * 1024 + col);
                float2 xb = *(const float2*)(xres + (size_t)rb * 1024 + col);
                *(float2*)(yout + (size_t)ra * 1024 + col) = make_float2(c0 + b0 + xa.x, c1 + b1 + xa.y);
                *(float2*)(yout + (size_t)rb * 1024 + col) = make_float2(c2 + b0 + xb.x, c3 + b1 + xb.y);
            }
        }
    }
}

// ==================== K2: per-chunk local state from zero (+decay products folded) ====================
__global__ void __launch_bounds__(256, 2) chunk_local_kernel() {
    const int c = blockIdx.x, b = blockIdx.y;
    const int tid = threadIdx.x;
    const int j = tid & 127;
    const int half = tid >> 7;
    const int sb = half * 64;

    __shared__ __align__(16) float buf[2][512];
    const float* base = g_qkvg + (size_t)(b * TLEN + c * CH) * 512;

    ((float2*)buf[0])[tid] = ((const float2*)base)[tid];
    __syncthreads();

    unsigned long long st2[32];
    #pragma unroll
    for (int i = 0; i < 32; i++) st2[i] = 0ull;
    float prod = 1.0f;

    for (int t = 0; t < CH; t++) {
        const float* cur = buf[t & 1];
        if (t + 1 < CH)
            ((float2*)buf[(t + 1) & 1])[tid] = ((const float2*)(base + (size_t)(t + 1) * 512))[tid];

        float vj = cur[256 + j];
        if (half == 0) prod *= cur[384 + j];
        unsigned long long vd = pk2(vj, vj);
        #pragma unroll
        for (int sq = 0; sq < 16; sq++) {
            int s = sb + sq * 4;
            ulonglong2 g4 = *(const ulonglong2*)&cur[384 + s];
            ulonglong2 k4 = *(const ulonglong2*)&cur[128 + s];
            st2[2 * sq]     = fma2(g4.x, st2[2 * sq],     mul2(k4.x, vd));
            st2[2 * sq + 1] = fma2(g4.y, st2[2 * sq + 1], mul2(k4.y, vd));
        }
        __syncthreads();
    }

    float* out = g_states + ((size_t)(b * NCH + c) * SDIM + sb) * SDIM + j;
    #pragma unroll
    for (int sp = 0; sp < 32; sp++) {
        float lo, hi;
        upk2(st2[sp], lo, hi);
        out[(size_t)(2 * sp) * SDIM]     = lo;
        out[(size_t)(2 * sp + 1) * SDIM] = hi;
    }
    if (half == 0) g_Dprod[(b * NCH + c) * SDIM + j] = prod;
}

// ==================== K3: sequential scan over chunks ====================
__global__ void scan_states_kernel() {
    const int b = blockIdx.y;
    const int pos = blockIdx.x * 256 + threadIdx.x;
    const int s = pos >> 7, j = pos & 127;
    float run = 0.f;
    for (int c = 0; c < NCH; c++) {
        size_t off = ((size_t)(b * NCH + c) * SDIM + s) * SDIM + j;
        float local = g_states[off];
        g_states[off] = run;
        run = g_Dprod[(b * NCH + c) * SDIM + s] * run + local;
    }
}

// ==================== K4: chunk replay with outputs ====================
__global__ void __launch_bounds__(256, 2) chunk_out_kernel() {
    const int c = blockIdx.x, b = blockIdx.y;
    const int tid = threadIdx.x;
    const int j = tid & 127;
    const int half = tid >> 7;
    const int sb = half * 64;

    __shared__ __align__(16) float buf[2][512];
    __shared__ float po[128];

    const float* base = g_qkvg + (size_t)(b * TLEN + c * CH) * 512;
    float* aout = g_attn + (size_t)(b * TLEN + c * CH) * SDIM;

    const float* sin = g_states + ((size_t)(b * NCH + c) * SDIM + sb) * SDIM + j;
    unsigned long long st2[32];
    #pragma unroll
    for (int sp = 0; sp < 32; sp++)
        st2[sp] = pk2(sin[(size_t)(2 * sp) * SDIM], sin[(size_t)(2 * sp + 1) * SDIM]);

    ((float2*)buf[0])[tid] = ((const float2*)base)[tid];
    __syncthreads();

    for (int t = 0; t < CH; t++) {
        const float* cur = buf[t & 1];
        if (t + 1 < CH)
            ((float2*)buf[(t + 1) & 1])[tid] = ((const float2*)(base + (size_t)(t + 1) * 512))[tid];

        float vj = cur[256 + j];
        unsigned long long vd = pk2(vj, vj);
        unsigned long long accA = 0ull, accB = 0ull;
        #pragma unroll
        for (int sq = 0; sq < 16; sq++) {
            int s = sb + sq * 4;
            ulonglong2 g4 = *(const ulonglong2*)&cur[384 + s];
            ulonglong2 k4 = *(const ulonglong2*)&cur[128 + s];
            ulonglong2 q4 = *(const ulonglong2*)&cur[s];
            st2[2 * sq]     = fma2(g4.x, st2[2 * sq],     mul2(k4.x, vd));
            st2[2 * sq + 1] = fma2(g4.y, st2[2 * sq + 1], mul2(k4.y, vd));
            accA = fma2(q4.x, st2[2 * sq],     accA);
            accB = fma2(q4.y, st2[2 * sq + 1], accB);
        }
        unsigned long long accT = add2(accA, accB);
        float lo, hi;
        upk2(accT, lo, hi);
        float part = lo + hi;

        if (half == 0) po[j] = part;
        __syncthreads();
        if (half == 1) aout[(size_t)t * SDIM + j] = part + po[j];
        __syncthreads();
    }
}

// ==================== K6: LayerNorm in place on d_out ====================
__global__ void ln_kernel(const float* __restrict__ gamma, const float* __restrict__ beta,
                          float* __restrict__ y) {
    const int row = blockIdx.x;
    const int tid = threadIdx.x;  // 256
    float4 v = ((float4*)y)[(size_t)row * 256 + tid];
    float s  = v.x + v.y + v.z + v.w;
    float sq = v.x * v.x + v.y * v.y + v.z * v.z + v.w * v.w;
    #pragma unroll
    for (int o = 16; o; o >>= 1) {
        s  += __shfl_xor_sync(0xffffffffu, s, o);
        sq += __shfl_xor_sync(0xffffffffu, sq, o);
    }
    __shared__ float ws[8], wq[8];
    int w = tid >> 5, l = tid & 31;
    if (l == 0) { ws[w] = s; wq[w] = sq; }
    __syncthreads();
    if (tid < 32) {
        s  = (tid < 8) ? ws[tid] : 0.f;
        sq = (tid < 8) ? wq[tid] : 0.f;
        #pragma unroll
        for (int o = 4; o; o >>= 1) {
            s  += __shfl_xor_sync(0xffffffffu, s, o);
            sq += __shfl_xor_sync(0xffffffffu, sq, o);
        }
        if (tid == 0) { ws[0] = s; wq[0] = sq; }
    }
    __syncthreads();
    const float mu = ws[0] * (1.0f / 1024.0f);
    const float var = wq[0] * (1.0f / 1024.0f) - mu * mu;
    const float rs = rsqrtf(var + 1e-5f);
    const int n = tid * 4;
    v.x = (v.x - mu) * rs * gamma[n + 0] + beta[n + 0];
    v.y = (v.y - mu) * rs * gamma[n + 1] + beta[n + 1];
    v.z = (v.z - mu) * rs * gamma[n + 2] + beta[n + 2];
    v.w = (v.w - mu) * rs * gamma[n + 3] + beta[n + 3];
    ((float4*)y)[(size_t)row * 256 + tid] = v;
}

// ==================== launch ====================
#define GEMM_SMEM (65536 + 1024)

extern "C" void kernel_launch(void* const* d_in, const int* in_sizes, int n_in,
                              void* d_out, int out_size) {
    const float* x     = (const float*)d_in[0];
    const float* Wq    = (const float*)d_in[1];
    const float* bq    = (const float*)d_in[2];
    const float* Wk    = (const float*)d_in[3];
    const float* bk    = (const float*)d_in[4];
    const float* Wv    = (const float*)d_in[5];
    const float* bv    = (const float*)d_in[6];
    const float* Wg    = (const float*)d_in[7];
    const float* bg    = (const float*)d_in[8];
    const float* Wo    = (const float*)d_in[9];
    const float* bo    = (const float*)d_in[10];
    const float* gamma = (const float*)d_in[11];
    const float* beta  = (const float*)d_in[12];
    float* out = (float*)d_out;

    cudaFuncSetAttribute(gemm_hmma<1024, 0>, cudaFuncAttributeMaxDynamicSharedMemorySize, GEMM_SMEM);
    cudaFuncSetAttribute(gemm_hmma<128, 1>,  cudaFuncAttributeMaxDynamicSharedMemorySize, GEMM_SMEM);

    pack_w_kernel<<<(512 * 1024 + 255) / 256, 256>>>(Wq, Wk, Wv, Wg, bq, bk, bv, bg);
    pack_wo_kernel<<<(1024 * 128 + 255) / 256, 256>>>(Wo);
    split_x_kernel<<<MROWS * DDIM / 4 / 256, 256>>>(x);

    gemm_hmma<1024, 0><<<dim3(MROWS / 128, 4), 256, GEMM_SMEM>>>(nullptr, nullptr, nullptr);

    chunk_local_kernel<<<dim3(NCH, BATCH), 256>>>();
    scan_states_kernel<<<dim3(SDIM * SDIM / 256, BATCH), 256>>>();
    chunk_out_kernel<<<dim3(NCH, BATCH), 256>>>();

    split_attn_kernel<<<MROWS * SDIM / 4 / 256, 256>>>();
    gemm_hmma<128, 1><<<dim3(MROWS / 128, 8), 256, GEMM_SMEM>>>(bo, x, out);

    ln_kernel<<<MROWS, 256>>>(gamma, beta, out);
}

// round 15
// speedup vs baseline: 1.0073x; 1.0004x over previous
#include <cuda_runtime.h>
#include <cuda_bf16.h>
#include <math.h>
#include <stdint.h>

#define BATCH 8
#define TLEN 4096
#define DDIM 1024
#define SDIM 128
#define CH   128
#define NCH  32
#define MROWS 32768

// ==================== helpers ====================
__device__ __forceinline__ uint32_t smem_u32(const void* p) {
    uint32_t a;
    asm("{ .reg .u64 t; cvta.to.shared.u64 t, %1; cvt.u32.u64 %0, t; }" : "=r"(a) : "l"(p));
    return a;
}
#define SWZ128(off) ((off) ^ (((off) >> 3) & 0x70))

#define CP_ASYNC16(saddr, gptr) \
    asm volatile("cp.async.cg.shared.global [%0], [%1], 16;" :: "r"(saddr), "l"(gptr))
#define CP_COMMIT() asm volatile("cp.async.commit_group;" ::: "memory")
#define CP_WAIT1() asm volatile("cp.async.wait_group 1;" ::: "memory")
#define CP_WAIT0() asm volatile("cp.async.wait_group 0;" ::: "memory")

__device__ __forceinline__ void ldsm4(uint32_t* r, uint32_t addr) {
    asm volatile("ldmatrix.sync.aligned.m8n8.x4.shared.b16 {%0,%1,%2,%3}, [%4];"
        : "=r"(r[0]), "=r"(r[1]), "=r"(r[2]), "=r"(r[3]) : "r"(addr));
}
__device__ __forceinline__ void mma_bf16(float* c, const uint32_t* a, const uint32_t* b) {
    asm volatile("mma.sync.aligned.m16n8k16.row.col.f32.bf16.bf16.f32 "
        "{%0,%1,%2,%3}, {%4,%5,%6,%7}, {%8,%9}, {%0,%1,%2,%3};"
        : "+f"(c[0]), "+f"(c[1]), "+f"(c[2]), "+f"(c[3])
        : "r"(a[0]), "r"(a[1]), "r"(a[2]), "r"(a[3]), "r"(b[0]), "r"(b[1]));
}

// ==================== packed f32x2 helpers ====================
__device__ __forceinline__ unsigned long long pk2(float lo, float hi) {
    unsigned long long r; asm("mov.b64 %0, {%1, %2};" : "=l"(r) : "f"(lo), "f"(hi)); return r;
}
__device__ __forceinline__ void upk2(unsigned long long v, float& lo, float& hi) {
    asm("mov.b64 {%0, %1}, %2;" : "=f"(lo), "=f"(hi) : "l"(v));
}
__device__ __forceinline__ unsigned long long fma2(unsigned long long a, unsigned long long b, unsigned long long c) {
    unsigned long long d; asm("fma.rn.f32x2 %0, %1, %2, %3;" : "=l"(d) : "l"(a), "l"(b), "l"(c)); return d;
}
__device__ __forceinline__ unsigned long long mul2(unsigned long long a, unsigned long long b) {
    unsigned long long d; asm("mul.rn.f32x2 %0, %1, %2;" : "=l"(d) : "l"(a), "l"(b)); return d;
}
__device__ __forceinline__ unsigned long long add2(unsigned long long a, unsigned long long b) {
    unsigned long long d; asm("add.rn.f32x2 %0, %1, %2;" : "=l"(d) : "l"(a), "l"(b)); return d;
}

// ==================== device scratch ====================
__device__ __align__(16) __nv_bfloat16 g_xhi[(size_t)MROWS * DDIM];   // 64 MB
__device__ __align__(16) __nv_bfloat16 g_xlo[(size_t)MROWS * DDIM];   // 64 MB
__device__ __align__(16) __nv_bfloat16 g_ahi[(size_t)MROWS * SDIM];   // 8 MB
__device__ __align__(16) __nv_bfloat16 g_alo[(size_t)MROWS * SDIM];   // 8 MB
__device__ __align__(16) __nv_bfloat16 g_Wt[512 * 3072];              // [n][hi|lo|hi] k-concat
__device__ __align__(16) __nv_bfloat16 g_Wot[1024 * 384];             // [n][hi|lo|hi]
__device__ float g_bcat[512];
__device__ __align__(16) float g_qkvg[(size_t)MROWS * 512];           // q|k|v|sig(g)
__device__ float g_states[(size_t)BATCH * NCH * SDIM * SDIM];
__device__ float g_Dprod[BATCH * NCH * SDIM];
__device__ __align__(16) float g_attn[(size_t)MROWS * SDIM];

// ==================== K0a: pack projection weights (bf16 split, transposed+concat) ====================
__global__ void pack_w_kernel(const float* __restrict__ Wq, const float* __restrict__ Wk,
                              const float* __restrict__ Wv, const float* __restrict__ Wg,
                              const float* __restrict__ bq, const float* __restrict__ bk,
                              const float* __restrict__ bv, const float* __restrict__ bg) {
    int idx = blockIdx.x * 256 + threadIdx.x;
    if (idx < 512 * 1024) {
        int n = idx >> 10, k = idx & 1023;
        int which = n >> 7, s = n & 127;
        const float* W = (which == 0) ? Wq : (which == 1) ? Wk : (which == 2) ? Wv : Wg;
        float w = W[k * SDIM + s];
        __nv_bfloat16 h = __float2bfloat16(w);
        __nv_bfloat16 l = __float2bfloat16(w - __bfloat162float(h));
        size_t row = (size_t)n * 3072;
        g_Wt[row + k] = h;
        g_Wt[row + 1024 + k] = l;
        g_Wt[row + 2048 + k] = h;
    }
    if (idx < 512) {
        int which = idx >> 7, s = idx & 127;
        const float* bp = (which == 0) ? bq : (which == 1) ? bk : (which == 2) ? bv : bg;
        g_bcat[idx] = bp[s];
    }
}

// ==================== K0b: pack Wo ====================
__global__ void pack_wo_kernel(const float* __restrict__ Wo) {
    int idx = blockIdx.x * 256 + threadIdx.x;
    if (idx >= 1024 * 128) return;
    int n = idx >> 7, k = idx & 127;
    float w = Wo[k * 1024 + n];
    __nv_bfloat16 h = __float2bfloat16(w);
    __nv_bfloat16 l = __float2bfloat16(w - __bfloat162float(h));
    size_t row = (size_t)n * 384;
    g_Wot[row + k] = h;
    g_Wot[row + 128 + k] = l;
    g_Wot[row + 256 + k] = h;
}

// ==================== splitters ====================
__device__ __forceinline__ void split4(float4 v, uint2& ho, uint2& lo) {
    __nv_bfloat162 h01 = __floats2bfloat162_rn(v.x, v.y);
    __nv_bfloat162 h23 = __floats2bfloat162_rn(v.z, v.w);
    float2 f01 = __bfloat1622float2(h01);
    float2 f23 = __bfloat1622float2(h23);
    __nv_bfloat162 l01 = __floats2bfloat162_rn(v.x - f01.x, v.y - f01.y);
    __nv_bfloat162 l23 = __floats2bfloat162_rn(v.z - f23.x, v.w - f23.y);
    ho.x = *(uint32_t*)&h01; ho.y = *(uint32_t*)&h23;
    lo.x = *(uint32_t*)&l01; lo.y = *(uint32_t*)&l23;
}

__global__ void split_x_kernel(const float* __restrict__ x) {
    size_t i = (size_t)blockIdx.x * 256 + threadIdx.x;
    float4 v = ((const float4*)x)[i];
    uint2 ho, lo;
    split4(v, ho, lo);
    ((uint2*)g_xhi)[i] = ho;
    ((uint2*)g_xlo)[i] = lo;
}

__global__ void split_attn_kernel() {
    size_t i = (size_t)blockIdx.x * 256 + threadIdx.x;
    float4 v = ((const float4*)g_attn)[i];
    uint2 ho, lo;
    split4(v, ho, lo);
    ((uint2*)g_ahi)[i] = ho;
    ((uint2*)g_alo)[i] = lo;
}

// ==================== HMMA GEMM (bf16x3 split, fp32 accum) ====================
// CTA tile 128x128, 8 warps (4M x 2N, warp tile 32x64), k-chunks of 64 bf16,
// double-buffered smem via cp.async. SW128 swizzle (128B rows).
// EPI 0: C = Xsplit @ Wt  -> bias, sigmoid on g block, write g_qkvg (fp32)
// EPI 1: C = Asplit @ Wot -> + bo + x residual, write yout (fp32)
template<int K0, int EPI>
__global__ void __launch_bounds__(256, 2) gemm_hmma(const float* __restrict__ bias_p,
                                                    const float* __restrict__ xres,
                                                    float* __restrict__ yout) {
    constexpr int CPS = K0 / 64;
    constexpr int NCHUNK = 3 * CPS;
    constexpr int LDB = 3 * K0;
    const __nv_bfloat16* Ahi = (EPI == 0) ? g_xhi : g_ahi;
    const __nv_bfloat16* Alo = (EPI == 0) ? g_xlo : g_alo;
    const __nv_bfloat16* Bc  = (EPI == 0) ? g_Wt  : g_Wot;

    extern __shared__ char smem_raw[];
    const uint32_t sbase = (smem_u32(smem_raw) + 1023) & ~1023u;
    // stage s: A at sbase + s*32768 (16KB), B at +16384 (16KB)

    const int tid = threadIdx.x;
    const int lane = tid & 31, wid = tid >> 5;
    const int bm = blockIdx.x, bn = blockIdx.y;
    const int wm = wid & 3, wn = wid >> 2;
    const int lrow = tid >> 3;     // 0..31
    const int lc16 = tid & 7;      // 16B column

    auto load_chunk = [&](int c, int stage) {
        const int seg = c / CPS;
        const int koff = (c % CPS) * 64;
        const __nv_bfloat16* Aseg = (seg < 2) ? Ahi : Alo;
        const uint32_t sA = sbase + stage * 32768;
        const uint32_t sB = sA + 16384;
        #pragma unroll
        for (int i = 0; i < 4; i++) {
            int row = i * 32 + lrow;
            const __nv_bfloat16* gp = Aseg + (size_t)(bm * 128 + row) * K0 + koff + lc16 * 8;
            CP_ASYNC16(sA + SWZ128((uint32_t)(row * 128 + lc16 * 16)), gp);
        }
        #pragma unroll
        for (int i = 0; i < 4; i++) {
            int row = i * 32 + lrow;
            const __nv_bfloat16* gp = Bc + (size_t)(bn * 128 + row) * LDB + seg * K0 + koff + lc16 * 8;
            CP_ASYNC16(sB + SWZ128((uint32_t)(row * 128 + lc16 * 16)), gp);
        }
        CP_COMMIT();
    };

    float acc[2][8][4];
    #pragma unroll
    for (int mi = 0; mi < 2; mi++)
        #pragma unroll
        for (int nf = 0; nf < 8; nf++)
            #pragma unroll
            for (int q = 0; q < 4; q++) acc[mi][nf][q] = 0.f;

    load_chunk(0, 0);

    #pragma unroll 1
    for (int c = 0; c < NCHUNK; c++) {
        const int stage = c & 1;
        if (c + 1 < NCHUNK) {
            load_chunk(c + 1, stage ^ 1);
            CP_WAIT1();
        } else {
            CP_WAIT0();
        }
        __syncthreads();

        const uint32_t sA = sbase + stage * 32768;
        const uint32_t sB = sA + 16384;
        const int krow = lane & 15;
        const int khalf = ((lane >> 4) & 1) * 16;

        #pragma unroll
        for (int ks = 0; ks < 4; ks++) {
            const int kb = ks * 32 + khalf;
            uint32_t af[2][4], bf[8][2];
            #pragma unroll
            for (int mi = 0; mi < 2; mi++) {
                int row = wm * 32 + mi * 16 + krow;
                ldsm4(af[mi], sA + SWZ128((uint32_t)(row * 128 + kb)));
            }
            #pragma unroll
            for (int gi = 0; gi < 4; gi++) {
                uint32_t r[4];
                int row = wn * 64 + gi * 16 + krow;
                ldsm4(r, sB + SWZ128((uint32_t)(row * 128 + kb)));
                bf[gi * 2][0]     = r[0]; bf[gi * 2][1]     = r[2];
                bf[gi * 2 + 1][0] = r[1]; bf[gi * 2 + 1][1] = r[3];
            }
            #pragma unroll
            for (int mi = 0; mi < 2; mi++)
                #pragma unroll
                for (int nf = 0; nf < 8; nf++)
                    mma_bf16(acc[mi][nf], af[mi], bf[nf]);
        }
        __syncthreads();
    }

    // ---- epilogue ----
    const int r0base = bm * 128 + wm * 32 + (lane >> 2);
    #pragma unroll
    for (int mi = 0; mi < 2; mi++) {
        const int ra = r0base + mi * 16;
        const int rb = ra + 8;
        #pragma unroll
        for (int nf = 0; nf < 8; nf++) {
            const int col = bn * 128 + wn * 64 + nf * 8 + (lane & 3) * 2;
            float c0 = acc[mi][nf][0], c1 = acc[mi][nf][1];
            float c2 = acc[mi][nf][2], c3 = acc[mi][nf][3];
            if (EPI == 0) {
                const float b0 = g_bcat[col], b1 = g_bcat[col + 1];
                float t0 = c0 + b0, t1 = c1 + b1, t2 = c2 + b0, t3 = c3 + b1;
                if (col >= 384) {
                    t0 = 1.0f / (1.0f + expf(-t0));
                    t1 = 1.0f / (1.0f + expf(-t1));
                    t2 = 1.0f / (1.0f + expf(-t2));
                    t3 = 1.0f / (1.0f + expf(-t3));
                }
                *(float2*)(g_qkvg + (size_t)ra * 512 + col) = make_float2(t0, t1);
                *(float2*)(g_qkvg + (size_t)rb * 512 + col) = make_float2(t2, t3);
            } else {
                const float b0 = bias_p[col], b1 = bias_p[col + 1];
                float2 xa = *(const float2*)(xres + (size_t)ra * 1024 + col);
                float2 xb = *(const float2*)(xres + (size_t)rb * 1024 + col);
                *(float2*)(yout + (size_t)ra * 1024 + col) = make_float2(c0 + b0 + xa.x, c1 + b1 + xa.y);
                *(float2*)(yout + (size_t)rb * 1024 + col) = make_float2(c2 + b0 + xb.x, c3 + b1 + xb.y);
            }
        }
    }
}

// ==================== K2: per-chunk local state from zero (+decay products folded) ====================
__global__ void __launch_bounds__(256, 2) chunk_local_kernel() {
    const int c = blockIdx.x, b = blockIdx.y;
    const int tid = threadIdx.x;
    const int j = tid & 127;
    const int half = tid >> 7;
    const int sb = half * 64;

    __shared__ __align__(16) float buf[2][512];
    const float* base = g_qkvg + (size_t)(b * TLEN + c * CH) * 512;

    ((float2*)buf[0])[tid] = ((const float2*)base)[tid];
    __syncthreads();

    unsigned long long st2[32];
    #pragma unroll
    for (int i = 0; i < 32; i++) st2[i] = 0ull;
    float prod = 1.0f;

    for (int t = 0; t < CH; t++) {
        const float* cur = buf[t & 1];
        if (t + 1 < CH)
            ((float2*)buf[(t + 1) & 1])[tid] = ((const float2*)(base + (size_t)(t + 1) * 512))[tid];

        float vj = cur[256 + j];
        if (half == 0) prod *= cur[384 + j];
        unsigned long long vd = pk2(vj, vj);
        #pragma unroll
        for (int sq = 0; sq < 16; sq++) {
            int s = sb + sq * 4;
            ulonglong2 g4 = *(const ulonglong2*)&cur[384 + s];
            ulonglong2 k4 = *(const ulonglong2*)&cur[128 + s];
            st2[2 * sq]     = fma2(g4.x, st2[2 * sq],     mul2(k4.x, vd));
            st2[2 * sq + 1] = fma2(g4.y, st2[2 * sq + 1], mul2(k4.y, vd));
        }
        __syncthreads();
    }

    float* out = g_states + ((size_t)(b * NCH + c) * SDIM + sb) * SDIM + j;
    #pragma unroll
    for (int sp = 0; sp < 32; sp++) {
        float lo, hi;
        upk2(st2[sp], lo, hi);
        out[(size_t)(2 * sp) * SDIM]     = lo;
        out[(size_t)(2 * sp + 1) * SDIM] = hi;
    }
    if (half == 0) g_Dprod[(b * NCH + c) * SDIM + j] = prod;
}

// ==================== K3: sequential scan over chunks ====================
__global__ void scan_states_kernel() {
    const int b = blockIdx.y;
    const int pos = blockIdx.x * 256 + threadIdx.x;
    const int s = pos >> 7, j = pos & 127;
    float run = 0.f;
    for (int c = 0; c < NCH; c++) {
        size_t off = ((size_t)(b * NCH + c) * SDIM + s) * SDIM + j;
        float local = g_states[off];
        g_states[off] = run;
        run = g_Dprod[(b * NCH + c) * SDIM + s] * run + local;
    }
}

// ==================== K4: chunk replay with outputs ====================
__global__ void __launch_bounds__(256, 2) chunk_out_kernel() {
    const int c = blockIdx.x, b = blockIdx.y;
    const int tid = threadIdx.x;
    const int j = tid & 127;
    const int half = tid >> 7;
    const int sb = half * 64;

    __shared__ __align__(16) float buf[2][512];
    __shared__ float po[128];

    const float* base = g_qkvg + (size_t)(b * TLEN + c * CH) * 512;
    float* aout = g_attn + (size_t)(b * TLEN + c * CH) * SDIM;

    const float* sin = g_states + ((size_t)(b * NCH + c) * SDIM + sb) * SDIM + j;
    unsigned long long st2[32];
    #pragma unroll
    for (int sp = 0; sp < 32; sp++)
        st2[sp] = pk2(sin[(size_t)(2 * sp) * SDIM], sin[(size_t)(2 * sp + 1) * SDIM]);

    ((float2*)buf[0])[tid] = ((const float2*)base)[tid];
    __syncthreads();

    for (int t = 0; t < CH; t++) {
        const float* cur = buf[t & 1];
        if (t + 1 < CH)
            ((float2*)buf[(t + 1) & 1])[tid] = ((const float2*)(base + (size_t)(t + 1) * 512))[tid];

        float vj = cur[256 + j];
        unsigned long long vd = pk2(vj, vj);
        unsigned long long accA = 0ull, accB = 0ull;
        #pragma unroll
        for (int sq = 0; sq < 16; sq++) {
            int s = sb + sq * 4;
            ulonglong2 g4 = *(const ulonglong2*)&cur[384 + s];
            ulonglong2 k4 = *(const ulonglong2*)&cur[128 + s];
            ulonglong2 q4 = *(const ulonglong2*)&cur[s];
            st2[2 * sq]     = fma2(g4.x, st2[2 * sq],     mul2(k4.x, vd));
            st2[2 * sq + 1] = fma2(g4.y, st2[2 * sq + 1], mul2(k4.y, vd));
            accA = fma2(q4.x, st2[2 * sq],     accA);
            accB = fma2(q4.y, st2[2 * sq + 1], accB);
        }
        unsigned long long accT = add2(accA, accB);
        float lo, hi;
        upk2(accT, lo, hi);
        float part = lo + hi;

        if (half == 0) po[j] = part;
        __syncthreads();
        if (half == 1) aout[(size_t)t * SDIM + j] = part + po[j];
        __syncthreads();
    }
}

// ==================== K6: LayerNorm in place on d_out ====================
__global__ void ln_kernel(const float* __restrict__ gamma, const float* __restrict__ beta,
                          float* __restrict__ y) {
    const int row = blockIdx.x;
    const int tid = threadIdx.x;  // 256
    float4 v = ((float4*)y)[(size_t)row * 256 + tid];
    float s  = v.x + v.y + v.z + v.w;
    float sq = v.x * v.x + v.y * v.y + v.z * v.z + v.w * v.w;
    #pragma unroll
    for (int o = 16; o; o >>= 1) {
        s  += __shfl_xor_sync(0xffffffffu, s, o);
        sq += __shfl_xor_sync(0xffffffffu, sq, o);
    }
    __shared__ float ws[8], wq[8];
    int w = tid >> 5, l = tid & 31;
    if (l == 0) { ws[w] = s; wq[w] = sq; }
    __syncthreads();
    if (tid < 32) {
        s  = (tid < 8) ? ws[tid] : 0.f;
        sq = (tid < 8) ? wq[tid] : 0.f;
        #pragma unroll
        for (int o = 4; o; o >>= 1) {
            s  += __shfl_xor_sync(0xffffffffu, s, o);
            sq += __shfl_xor_sync(0xffffffffu, sq, o);
        }
        if (tid == 0) { ws[0] = s; wq[0] = sq; }
    }
    __syncthreads();
    const float mu = ws[0] * (1.0f / 1024.0f);
    const float var = wq[0] * (1.0f / 1024.0f) - mu * mu;
    const float rs = rsqrtf(var + 1e-5f);
    const int n = tid * 4;
    v.x = (v.x - mu) * rs * gamma[n + 0] + beta[n + 0];
    v.y = (v.y - mu) * rs * gamma[n + 1] + beta[n + 1];
    v.z = (v.z - mu) * rs * gamma[n + 2] + beta[n + 2];
    v.w = (v.w - mu) * rs * gamma[n + 3] + beta[n + 3];
    ((float4*)y)[(size_t)row * 256 + tid] = v;
}

// ==================== launch ====================
#define GEMM_SMEM (65536 + 1024)

extern "C" void kernel_launch(void* const* d_in, const int* in_sizes, int n_in,
                              void* d_out, int out_size) {
    const float* x     = (const float*)d_in[0];
    const float* Wq    = (const float*)d_in[1];
    const float* bq    = (const float*)d_in[2];
    const float* Wk    = (const float*)d_in[3];
    const float* bk    = (const float*)d_in[4];
    const float* Wv    = (const float*)d_in[5];
    const float* bv    = (const float*)d_in[6];
    const float* Wg    = (const float*)d_in[7];
    const float* bg    = (const float*)d_in[8];
    const float* Wo    = (const float*)d_in[9];
    const float* bo    = (const float*)d_in[10];
    const float* gamma = (const float*)d_in[11];
    const float* beta  = (const float*)d_in[12];
    float* out = (float*)d_out;

    cudaFuncSetAttribute(gemm_hmma<1024, 0>, cudaFuncAttributeMaxDynamicSharedMemorySize, GEMM_SMEM);
    cudaFuncSetAttribute(gemm_hmma<128, 1>,  cudaFuncAttributeMaxDynamicSharedMemorySize, GEMM_SMEM);

    pack_w_kernel<<<(512 * 1024 + 255) / 256, 256>>>(Wq, Wk, Wv, Wg, bq, bk, bv, bg);
    pack_wo_kernel<<<(1024 * 128 + 255) / 256, 256>>>(Wo);
    split_x_kernel<<<MROWS * DDIM / 4 / 256, 256>>>(x);

    gemm_hmma<1024, 0><<<dim3(MROWS / 128, 4), 256, GEMM_SMEM>>>(nullptr, nullptr, nullptr);

    chunk_local_kernel<<<dim3(NCH, BATCH), 256>>>();
    scan_states_kernel<<<dim3(SDIM * SDIM / 256, BATCH), 256>>>();
    chunk_out_kernel<<<dim3(NCH, BATCH), 256>>>();

    split_attn_kernel<<<MROWS * SDIM / 4 / 256, 256>>>();
    gemm_hmma<128, 1><<<dim3(MROWS / 128, 8), 256, GEMM_SMEM>>>(bo, x, out);

    ln_kernel<<<MROWS, 256>>>(gamma, beta, out);
}